// round 16
// baseline (speedup 1.0000x reference)
#include <cuda_runtime.h>
#include <cuda_bf16.h>
#include <cstdint>
#include <math.h>

// Shapes fixed: ts/note (512,16,128) fp32 -> N=8192, D=128
#define NTOT 8192
#define DDIM 128
#define INVT 100.0f
#define TPC 19                    // tiles per CTA (tile = 128 rows x 64 cols)
#define NTILES 8192               // 64 row-tiles x 128 col-tiles
#define NCTA ((NTILES + TPC - 1) / TPC)   // 432

// ---------------- device globals (no dynamic alloc allowed) ----------------
__device__ __align__(16) __nv_bfloat16 g_tsb[NTOT * DDIM];
__device__ __align__(16) __nv_bfloat16 g_ntb[NTOT * DDIM];
__device__ float g_diag[NTOT];
__device__ __align__(16) float2 g_rowp[NTOT][16];    // [row][slot*2 + nwarp]
__device__ __align__(16) float2 g_colp[64][NTOT];    // [rt][col]
__device__ float g_bsum[32];
__device__ unsigned g_cnt;                            // zero-init; reset by last block

// ---------------- helpers ----------------
__device__ __forceinline__ uint32_t smem_u32(const void* p) {
    uint32_t a;
    asm("{ .reg .u64 t; cvta.to.shared.u64 t, %1; cvt.u32.u64 %0, t; }" : "=r"(a) : "l"(p));
    return a;
}
// swizzle for 256B rows: XOR 16B-unit index bits[6:4] with row&7 (bits[10:8])
#define SWZ(off) ((off) ^ (((off) >> 4) & 0x70u))

__device__ __forceinline__ void ldsm_x4(uint32_t* r, uint32_t addr) {
    asm volatile("ldmatrix.sync.aligned.m8n8.x4.shared.b16 {%0,%1,%2,%3}, [%4];"
        : "=r"(r[0]), "=r"(r[1]), "=r"(r[2]), "=r"(r[3]) : "r"(addr));
}
__device__ __forceinline__ void mma_bf16(float* c, const uint32_t* a, const uint32_t* b) {
    asm volatile("mma.sync.aligned.m16n8k16.row.col.f32.bf16.bf16.f32 "
        "{%0,%1,%2,%3}, {%4,%5,%6,%7}, {%8,%9}, {%0,%1,%2,%3};"
        : "+f"(c[0]), "+f"(c[1]), "+f"(c[2]), "+f"(c[3])
        : "r"(a[0]), "r"(a[1]), "r"(a[2]), "r"(a[3]), "r"(b[0]), "r"(b[1]));
}
// A tile: 32KB (128 rows x 256B), 8 x 16B per thread
__device__ __forceinline__ void pf_a(uint32_t sdst, const __nv_bfloat16* src, int tid) {
    const char* s = (const char*)src;
    #pragma unroll
    for (int i = 0; i < 8; i++) {
        uint32_t g = (uint32_t)tid * 8u + i;
        uint32_t off = (g >> 4) * 256u + (g & 15u) * 16u;
        asm volatile("cp.async.cg.shared.global [%0], [%1], 16;" :: "r"(sdst + SWZ(off)), "l"(s + off) : "memory");
    }
}
// B tile: 16KB (64 n-rows x 256B), 4 x 16B per thread
__device__ __forceinline__ void pf_b(uint32_t sdst, const __nv_bfloat16* src, int tid) {
    const char* s = (const char*)src;
    #pragma unroll
    for (int i = 0; i < 4; i++) {
        uint32_t g = (uint32_t)tid * 4u + i;
        uint32_t off = (g >> 4) * 256u + (g & 15u) * 16u;
        asm volatile("cp.async.cg.shared.global [%0], [%1], 16;" :: "r"(sdst + SWZ(off)), "l"(s + off) : "memory");
    }
}
__device__ __forceinline__ void lse_merge(float& M, float& S, float m2, float s2) {
    if (m2 > M) { S = S * __expf(M - m2) + s2; M = m2; }
    else if (m2 != -INFINITY) S += s2 * __expf(m2 - M);
}

// ============ kernel 1: fp32 -> bf16 row-major + g_rowp init ============
__global__ void conv_kernel(const float* __restrict__ ts, const float* __restrict__ nt) {
    int id = blockIdx.x * blockDim.x + threadIdx.x;  // 262144
    if (id < NTOT * 16)
        ((float2*)g_rowp)[id] = make_float2(-INFINITY, 0.0f);
    int mat = id >> 17;
    int r = id & 131071;
    int row = r >> 4, g = r & 15;
    const float* src = (mat ? nt : ts) + (size_t)row * DDIM + g * 8;
    float4 v0 = *(const float4*)(src);
    float4 v1 = *(const float4*)(src + 4);
    __nv_bfloat162 b0 = __floats2bfloat162_rn(v0.x, v0.y);
    __nv_bfloat162 b1 = __floats2bfloat162_rn(v0.z, v0.w);
    __nv_bfloat162 b2 = __floats2bfloat162_rn(v1.x, v1.y);
    __nv_bfloat162 b3 = __floats2bfloat162_rn(v1.z, v1.w);
    uint4 pk;
    pk.x = *(uint32_t*)&b0; pk.y = *(uint32_t*)&b1;
    pk.z = *(uint32_t*)&b2; pk.w = *(uint32_t*)&b3;
    uint4* dst = (uint4*)((mat ? g_ntb : g_tsb) + (size_t)row * DDIM) + g;
    *dst = pk;
}

// ============ kernel 2: GEMM + fused LSE, occupancy 3, ragged ranges ============
// grid NCTA=432: CTA k handles global tiles [k*TPC, min(k*TPC+TPC, 8192)).
// tile t: rt = t>>7 (row stripe of 128), ct = t&127 (64-col tile).
// All A fragments from smem (no areg) to fit 3 CTAs/SM; B double-buffered.
#define SMEM_A 0
#define SMEM_B 32768
#define SMEM_RED (32768 + 2 * 16384)
#define DYN_SMEM (SMEM_RED + 2 * 4096 + 1024)

__global__ void __launch_bounds__(256, 3) cont_mma() {
    extern __shared__ __align__(16) char smraw[];
    const uint32_t sb = (smem_u32(smraw) + 1023u) & ~1023u;
    const uint32_t sA = sb + SMEM_A;
    float2* red = (float2*)(smraw + ((sb - smem_u32(smraw)) + SMEM_RED));

    const int tid = threadIdx.x, lid = tid & 31, wid = tid >> 5;
    const int mwarp = wid >> 1, nwarp = wid & 1;
    const int k = blockIdx.x;
    const int s = k * TPC;
    const int e = min(s + TPC, NTILES);
    const int n = e - s;

    int rt = s >> 7;
    int r0 = rt << 7;
    int slot = k - (rt << 7) / TPC;

    // prologue: G0 = {A, B_0}
    pf_a(sA, g_tsb + (size_t)r0 * DDIM, tid);
    pf_b(sb + SMEM_B, g_ntb + (size_t)(s & 127) * 64 * DDIM, tid);
    asm volatile("cp.async.commit_group;" ::: "memory");

    const uint32_t X = (uint32_t)(lid & 7) << 4;
    const uint32_t cA = ((lid >> 4) & 1) * 16u;
    const uint32_t cB = ((lid >> 3) & 1) * 16u;
    uint32_t rowA[2], rowB[2];
    #pragma unroll
    for (int mt = 0; mt < 2; mt++)
        rowA[mt] = (uint32_t)(mwarp * 32 + mt * 16 + (lid & 15)) * 256u;
    #pragma unroll
    for (int np = 0; np < 2; np++)
        rowB[np] = (uint32_t)(nwarp * 32 + np * 16 + (lid & 7) + ((lid >> 4) & 1) * 8) * 256u;

    float m4[4], s4[4];
    #pragma unroll
    for (int i = 0; i < 4; i++) { m4[i] = -INFINITY; s4[i] = 0.0f; }

    int prt = 0, pcb = 0;     // prev tile rt / col base (for deferred merge)

    for (int i = 0; i < n; i++) {
        const int t = s + i;
        const int ct = t & 127;
        const bool crossing = (i > 0) && (ct == 0);
        const uint32_t sBuf = sb + SMEM_B + 16384u * (uint32_t)(i & 1);

        asm volatile("cp.async.wait_group 0;" ::: "memory");
        __syncthreads();   // B[i] (+A) visible; red[i-1] complete; buf (i+1)&1 free

        if (crossing) {
            // flush row-LSE state for the old rt (old slot), reset
            #pragma unroll
            for (int mt = 0; mt < 2; mt++)
            #pragma unroll
            for (int h = 0; h < 2; h++) {
                const int rs = mt * 2 + h;
                float m = m4[rs], ss = s4[rs];
                #pragma unroll
                for (int d = 1; d <= 2; d <<= 1) {
                    float om = __shfl_xor_sync(0xFFFFFFFFu, m, d);
                    float os = __shfl_xor_sync(0xFFFFFFFFu, ss, d);
                    lse_merge(m, ss, om, os);
                }
                if ((lid & 3) == 0) {
                    const int row = r0 + mwarp * 32 + mt * 16 + (lid >> 2) + h * 8;
                    g_rowp[row][slot * 2 + nwarp] = make_float2(m, ss);
                }
                m4[rs] = -INFINITY; s4[rs] = 0.0f;
            }
            // advance to new rt, reload A (own async group)
            rt = t >> 7;
            r0 = rt << 7;
            slot = k - (rt << 7) / TPC;
            pf_a(sA, g_tsb + (size_t)r0 * DDIM, tid);
            asm volatile("cp.async.commit_group;" ::: "memory");
        }

        // deferred column merge of tile i-1 (prev rt/cb)
        if (i > 0 && tid < 64) {
            const float2* rd = red + ((i - 1) & 1) * 512;
            float2 p0 = rd[tid * 4 + 0], p1 = rd[tid * 4 + 1];
            float2 p2 = rd[tid * 4 + 2], p3 = rd[tid * 4 + 3];
            float M = p0.x, S = p0.y;
            lse_merge(M, S, p1.x, p1.y);
            lse_merge(M, S, p2.x, p2.y);
            lse_merge(M, S, p3.x, p3.y);
            g_colp[prt][pcb + tid] = make_float2(M, S);
        }

        // single-ahead prefetch: B for tile i+1 into buf (i+1)&1 (free since barrier)
        if (i + 1 < n) {
            pf_b(sb + SMEM_B + 16384u * (uint32_t)((i + 1) & 1),
                 g_ntb + (size_t)((t + 1) & 127) * 64 * DDIM, tid);
            asm volatile("cp.async.commit_group;" ::: "memory");
        }

        if (crossing) {
            // A reload must land before mainloop; A committed before B[i+1]
            if (i + 1 < n) asm volatile("cp.async.wait_group 1;" ::: "memory");
            else           asm volatile("cp.async.wait_group 0;" ::: "memory");
            __syncthreads();   // all threads' A copies visible
        }

        float acc[2][4][4];
        #pragma unroll
        for (int mt = 0; mt < 2; mt++)
            #pragma unroll
            for (int nt = 0; nt < 4; nt++)
                #pragma unroll
                for (int q = 0; q < 4; q++) acc[mt][nt][q] = 0.0f;

        // k loop: A and B both from smem
        #pragma unroll
        for (int kt = 0; kt < 8; kt++) {
            const uint32_t kb = (uint32_t)kt * 32u;
            uint32_t bfr[4][2];
            #pragma unroll
            for (int np = 0; np < 2; np++) {
                uint32_t tt[4];
                ldsm_x4(tt, sBuf + rowB[np] + ((kb + cB) ^ X));
                bfr[np * 2][0] = tt[0]; bfr[np * 2][1] = tt[1];
                bfr[np * 2 + 1][0] = tt[2]; bfr[np * 2 + 1][1] = tt[3];
            }
            #pragma unroll
            for (int mt = 0; mt < 2; mt++) {
                uint32_t afr[4];
                ldsm_x4(afr, sA + rowA[mt] + ((kb + cA) ^ X));
                #pragma unroll
                for (int nt = 0; nt < 4; nt++)
                    mma_bf16(acc[mt][nt], afr, bfr[nt]);
            }
        }

        const int cb = ct * 64;
        const bool masked = ((unsigned)(cb - r0) < 128u);
        float cmx[8], csum[8];

        if (!masked) {
            // ---- row online LSE ----
            #pragma unroll
            for (int mt = 0; mt < 2; mt++)
            #pragma unroll
            for (int h = 0; h < 2; h++) {
                const int rs = mt * 2 + h;
                float amax = acc[mt][0][h * 2];
                #pragma unroll
                for (int nt = 0; nt < 4; nt++)
                    #pragma unroll
                    for (int c = 0; c < 2; c++)
                        amax = fmaxf(amax, acc[mt][nt][h * 2 + c]);
                const float vm = amax * INVT;
                if (vm > m4[rs]) { s4[rs] *= __expf(m4[rs] - vm); m4[rs] = vm; }
                const float thr = (m4[rs] - 25.0f) * (1.0f / INVT);
                #pragma unroll
                for (int nt = 0; nt < 4; nt++)
                    #pragma unroll
                    for (int c = 0; c < 2; c++) {
                        const float a = acc[mt][nt][h * 2 + c];
                        if (a > thr) s4[rs] += __expf(fmaf(a, INVT, -m4[rs]));
                    }
            }
            // ---- col tile max pass ----
            #pragma unroll
            for (int nt = 0; nt < 4; nt++)
            #pragma unroll
            for (int c = 0; c < 2; c++) {
                const int ix = nt * 2 + c;
                float v = acc[0][nt][c];
                v = fmaxf(v, acc[0][nt][2 + c]);
                v = fmaxf(v, acc[1][nt][c]);
                v = fmaxf(v, acc[1][nt][2 + c]);
                cmx[ix] = v;
            }
        } else {
            // ---- masked tile (rare): block-diag mask + diag capture ----
            #pragma unroll
            for (int mt = 0; mt < 2; mt++)
            #pragma unroll
            for (int h = 0; h < 2; h++) {
                const int rs = mt * 2 + h;
                const int gi = r0 + mwarp * 32 + mt * 16 + (lid >> 2) + h * 8;
                #pragma unroll
                for (int nt = 0; nt < 4; nt++)
                    #pragma unroll
                    for (int c = 0; c < 2; c++) {
                        const int gj = cb + nwarp * 32 + nt * 8 + (lid & 3) * 2 + c;
                        const float v = acc[mt][nt][h * 2 + c] * INVT;
                        const bool sameblk = (((gi ^ gj) >> 4) == 0);
                        const bool isdiag = (gi == gj);
                        if (isdiag) g_diag[gi] = v;
                        if (!sameblk || isdiag) {
                            if (v > m4[rs]) { s4[rs] = s4[rs] * __expf(m4[rs] - v) + 1.0f; m4[rs] = v; }
                            else if (v > m4[rs] - 25.0f) s4[rs] += __expf(v - m4[rs]);
                        }
                    }
            }
            #pragma unroll
            for (int nt = 0; nt < 4; nt++)
            #pragma unroll
            for (int c = 0; c < 2; c++) {
                const int ix = nt * 2 + c;
                const int gj = cb + nwarp * 32 + nt * 8 + (lid & 3) * 2 + c;
                float v = -INFINITY;
                #pragma unroll
                for (int mt = 0; mt < 2; mt++)
                    #pragma unroll
                    for (int h = 0; h < 2; h++) {
                        const int gi = r0 + mwarp * 32 + mt * 16 + (lid >> 2) + h * 8;
                        const bool keep = (((gi ^ gj) >> 4) != 0) || (gi == gj);
                        if (keep) v = fmaxf(v, acc[mt][nt][h * 2 + c]);
                    }
                cmx[ix] = v;
            }
        }

        // merge col max across the 8 lanes holding this column (lid>>2 varies)
        #pragma unroll
        for (int ix = 0; ix < 8; ix++) {
            #pragma unroll
            for (int d = 4; d <= 16; d <<= 1)
                cmx[ix] = fmaxf(cmx[ix], __shfl_xor_sync(0xFFFFFFFFu, cmx[ix], d));
        }
        // col sum pass (guarded exp)
        if (!masked) {
            #pragma unroll
            for (int nt = 0; nt < 4; nt++)
            #pragma unroll
            for (int c = 0; c < 2; c++) {
                const int ix = nt * 2 + c;
                const float ML = cmx[ix] * INVT;
                const float thr = cmx[ix] - 0.25f;
                float ss = 0.0f;
                #pragma unroll
                for (int mt = 0; mt < 2; mt++)
                    #pragma unroll
                    for (int h = 0; h < 2; h++) {
                        const float a = acc[mt][nt][h * 2 + c];
                        if (a > thr) ss += __expf(fmaf(a, INVT, -ML));
                    }
                csum[ix] = ss;
            }
        } else {
            #pragma unroll
            for (int nt = 0; nt < 4; nt++)
            #pragma unroll
            for (int c = 0; c < 2; c++) {
                const int ix = nt * 2 + c;
                const int gj = cb + nwarp * 32 + nt * 8 + (lid & 3) * 2 + c;
                const float ML = cmx[ix] * INVT;
                const float thr = cmx[ix] - 0.25f;
                float ss = 0.0f;
                #pragma unroll
                for (int mt = 0; mt < 2; mt++)
                    #pragma unroll
                    for (int h = 0; h < 2; h++) {
                        const int gi = r0 + mwarp * 32 + mt * 16 + (lid >> 2) + h * 8;
                        const bool keep = (((gi ^ gj) >> 4) != 0) || (gi == gj);
                        const float a = acc[mt][nt][h * 2 + c];
                        if (keep && a > thr) ss += __expf(fmaf(a, INVT, -ML));
                    }
                csum[ix] = ss;
            }
        }
        #pragma unroll
        for (int ix = 0; ix < 8; ix++) {
            #pragma unroll
            for (int d = 4; d <= 16; d <<= 1)
                csum[ix] += __shfl_xor_sync(0xFFFFFFFFu, csum[ix], d);
        }
        // write this tile's partials into red[i&1] (read next iteration)
        if (lid < 4) {
            float2* wr = red + (i & 1) * 512;
            #pragma unroll
            for (int nt = 0; nt < 4; nt++)
                #pragma unroll
                for (int c = 0; c < 2; c++)
                    wr[(nwarp * 32 + nt * 8 + lid * 2 + c) * 4 + mwarp] =
                        make_float2(cmx[nt * 2 + c] * INVT, csum[nt * 2 + c]);
        }

        prt = rt; pcb = cb;
    }

    // final tile's deferred merge
    __syncthreads();
    if (tid < 64) {
        const float2* rd = red + ((n - 1) & 1) * 512;
        float2 p0 = rd[tid * 4 + 0], p1 = rd[tid * 4 + 1];
        float2 p2 = rd[tid * 4 + 2], p3 = rd[tid * 4 + 3];
        float M = p0.x, S = p0.y;
        lse_merge(M, S, p1.x, p1.y);
        lse_merge(M, S, p2.x, p2.y);
        lse_merge(M, S, p3.x, p3.y);
        g_colp[prt][pcb + tid] = make_float2(M, S);
    }

    // final row flush (current rt / slot)
    #pragma unroll
    for (int mt = 0; mt < 2; mt++)
    #pragma unroll
    for (int h = 0; h < 2; h++) {
        const int rs = mt * 2 + h;
        float m = m4[rs], ss = s4[rs];
        #pragma unroll
        for (int d = 1; d <= 2; d <<= 1) {
            float om = __shfl_xor_sync(0xFFFFFFFFu, m, d);
            float os = __shfl_xor_sync(0xFFFFFFFFu, ss, d);
            lse_merge(m, ss, om, os);
        }
        if ((lid & 3) == 0) {
            const int row = r0 + mwarp * 32 + mt * 16 + (lid >> 2) + h * 8;
            g_rowp[row][slot * 2 + nwarp] = make_float2(m, ss);
        }
    }
}

// ============ kernel 3: per-index terms + full reduction (last-block) ============
__global__ void cont_fin(float* out) {
    __shared__ float rs[256];
    __shared__ bool last;
    const int tid = threadIdx.x;
    const int i = blockIdx.x * 256 + tid;

    // row LSE: 16 slots, two-pass (max then guarded sum; empty slots are -inf)
    float2 rp[16];
    float M = -INFINITY;
    #pragma unroll
    for (int kk = 0; kk < 16; kk++) { rp[kk] = g_rowp[i][kk]; M = fmaxf(M, rp[kk].x); }
    float S = 0.0f;
    #pragma unroll
    for (int kk = 0; kk < 16; kk++)
        if (rp[kk].x > M - 25.0f) S += rp[kk].y * __expf(rp[kk].x - M);
    const float lser = M + __logf(S);

    // col LSE: 64 partials, two-pass over L2-hot gmem
    float Mc = -INFINITY;
    #pragma unroll 8
    for (int p = 0; p < 64; p++) Mc = fmaxf(Mc, g_colp[p][i].x);
    float Sc = 0.0f;
    #pragma unroll 8
    for (int p = 0; p < 64; p++) {
        float2 q = g_colp[p][i];
        if (q.x > Mc - 25.0f) Sc += q.y * __expf(q.x - Mc);
    }
    const float lsec = Mc + __logf(Sc);

    rs[tid] = 0.5f * (lser + lsec) - g_diag[i];
    __syncthreads();
    for (int o = 128; o > 0; o >>= 1) {
        if (tid < o) rs[tid] += rs[tid + o];
        __syncthreads();
    }
    if (tid == 0) {
        g_bsum[blockIdx.x] = rs[0];
        __threadfence();
        last = (atomicAdd(&g_cnt, 1u) == gridDim.x - 1);
    }
    __syncthreads();
    if (last && tid < 32) {
        __threadfence();
        float v = g_bsum[tid];
        #pragma unroll
        for (int d = 16; d > 0; d >>= 1) v += __shfl_xor_sync(0xFFFFFFFFu, v, d);
        if (tid == 0) {
            float loss = v / (float)NTOT;
            if (isnan(loss) || isinf(loss)) loss = 0.0f;
            out[0] = loss;
            g_cnt = 0;   // reset for next (graph-replayed) launch
        }
    }
}

extern "C" void kernel_launch(void* const* d_in, const int* in_sizes, int n_in,
                              void* d_out, int out_size) {
    const float* ts = (const float*)d_in[0];
    const float* nt = (const float*)d_in[1];
    (void)in_sizes; (void)n_in; (void)out_size;

    conv_kernel<<<1024, 256>>>(ts, nt);
    cudaFuncSetAttribute(cont_mma, cudaFuncAttributeMaxDynamicSharedMemorySize, DYN_SMEM);
    cont_mma<<<NCTA, 256, DYN_SMEM>>>();
    cont_fin<<<32, 256>>>((float*)d_out);
}

// round 17
// speedup vs baseline: 1.0895x; 1.0895x over previous
#include <cuda_runtime.h>
#include <cuda_bf16.h>
#include <cstdint>
#include <math.h>

// Shapes fixed: ts/note (512,16,128) fp32 -> N=8192, D=128
#define NTOT 8192
#define DDIM 128
#define INVT 100.0f
#define NTILES 8192               // 64 row-tiles x 128 col-tiles (tile = 128x64)
#define NCTA 296                  // 148 SMs x 2 slots, perfectly balanced
// CTAs 0..199 take 28 tiles, CTAs 200..295 take 27 (200*28 + 96*27 = 8192)

__device__ __forceinline__ int cta_start(int k) {
    return k < 200 ? k * 28 : 5600 + (k - 200) * 27;
}
__device__ __forceinline__ int cta_of_tile(int t) {
    return t < 5600 ? t / 28 : 200 + (t - 5600) / 27;
}

// ---------------- device globals (no dynamic alloc allowed) ----------------
__device__ __align__(16) __nv_bfloat16 g_tsb[NTOT * DDIM];
__device__ __align__(16) __nv_bfloat16 g_ntb[NTOT * DDIM];
__device__ float g_diag[NTOT];
__device__ __align__(16) float2 g_rowp[NTOT][12];    // [row][slot*2 + nwarp]
__device__ __align__(16) float2 g_colp[64][NTOT];    // [rt][col]
__device__ float g_bsum[32];
__device__ unsigned g_cnt;                            // zero-init; reset by last block

// ---------------- helpers ----------------
__device__ __forceinline__ uint32_t smem_u32(const void* p) {
    uint32_t a;
    asm("{ .reg .u64 t; cvta.to.shared.u64 t, %1; cvt.u32.u64 %0, t; }" : "=r"(a) : "l"(p));
    return a;
}
// swizzle for 256B rows: XOR 16B-unit index bits[6:4] with row&7 (bits[10:8])
#define SWZ(off) ((off) ^ (((off) >> 4) & 0x70u))

__device__ __forceinline__ void ldsm_x4(uint32_t* r, uint32_t addr) {
    asm volatile("ldmatrix.sync.aligned.m8n8.x4.shared.b16 {%0,%1,%2,%3}, [%4];"
        : "=r"(r[0]), "=r"(r[1]), "=r"(r[2]), "=r"(r[3]) : "r"(addr));
}
__device__ __forceinline__ void mma_bf16(float* c, const uint32_t* a, const uint32_t* b) {
    asm volatile("mma.sync.aligned.m16n8k16.row.col.f32.bf16.bf16.f32 "
        "{%0,%1,%2,%3}, {%4,%5,%6,%7}, {%8,%9}, {%0,%1,%2,%3};"
        : "+f"(c[0]), "+f"(c[1]), "+f"(c[2]), "+f"(c[3])
        : "r"(a[0]), "r"(a[1]), "r"(a[2]), "r"(a[3]), "r"(b[0]), "r"(b[1]));
}
// A tile: 32KB (128 rows x 256B), 8 x 16B per thread
__device__ __forceinline__ void pf_a(uint32_t sdst, const __nv_bfloat16* src, int tid) {
    const char* s = (const char*)src;
    #pragma unroll
    for (int i = 0; i < 8; i++) {
        uint32_t g = (uint32_t)tid * 8u + i;
        uint32_t off = (g >> 4) * 256u + (g & 15u) * 16u;
        asm volatile("cp.async.cg.shared.global [%0], [%1], 16;" :: "r"(sdst + SWZ(off)), "l"(s + off) : "memory");
    }
}
// B tile: 16KB (64 n-rows x 256B), 4 x 16B per thread
__device__ __forceinline__ void pf_b(uint32_t sdst, const __nv_bfloat16* src, int tid) {
    const char* s = (const char*)src;
    #pragma unroll
    for (int i = 0; i < 4; i++) {
        uint32_t g = (uint32_t)tid * 4u + i;
        uint32_t off = (g >> 4) * 256u + (g & 15u) * 16u;
        asm volatile("cp.async.cg.shared.global [%0], [%1], 16;" :: "r"(sdst + SWZ(off)), "l"(s + off) : "memory");
    }
}
__device__ __forceinline__ void lse_merge(float& M, float& S, float m2, float s2) {
    if (m2 > M) { S = S * __expf(M - m2) + s2; M = m2; }
    else if (m2 != -INFINITY) S += s2 * __expf(m2 - M);
}

// ============ kernel 1: fp32 -> bf16 row-major + g_rowp init ============
__global__ void conv_kernel(const float* __restrict__ ts, const float* __restrict__ nt) {
    int id = blockIdx.x * blockDim.x + threadIdx.x;  // 262144
    if (id < NTOT * 12)
        ((float2*)g_rowp)[id] = make_float2(-INFINITY, 0.0f);
    int mat = id >> 17;
    int r = id & 131071;
    int row = r >> 4, g = r & 15;
    const float* src = (mat ? nt : ts) + (size_t)row * DDIM + g * 8;
    float4 v0 = *(const float4*)(src);
    float4 v1 = *(const float4*)(src + 4);
    __nv_bfloat162 b0 = __floats2bfloat162_rn(v0.x, v0.y);
    __nv_bfloat162 b1 = __floats2bfloat162_rn(v0.z, v0.w);
    __nv_bfloat162 b2 = __floats2bfloat162_rn(v1.x, v1.y);
    __nv_bfloat162 b3 = __floats2bfloat162_rn(v1.z, v1.w);
    uint4 pk;
    pk.x = *(uint32_t*)&b0; pk.y = *(uint32_t*)&b1;
    pk.z = *(uint32_t*)&b2; pk.w = *(uint32_t*)&b3;
    uint4* dst = (uint4*)((mat ? g_ntb : g_tsb) + (size_t)row * DDIM) + g;
    *dst = pk;
}

// ============ kernel 2: GEMM + fused LSE, balanced ragged tile ranges ============
// grid 296: CTA k handles tiles [cta_start(k), cta_start(k+1)) (28 or 27 tiles).
// tile t: rt = t>>7 (row stripe of 128), ct = t&127 (64-col tile).
// Crosses at most one rt boundary: flush row state, reload A, continue.
#define SMEM_A 0
#define SMEM_B 32768
#define SMEM_RED (32768 + 3 * 16384)
#define DYN_SMEM (SMEM_RED + 2 * 4096 + 1024)

__global__ void __launch_bounds__(256, 2) cont_mma() {
    extern __shared__ __align__(16) char smraw[];
    const uint32_t sb = (smem_u32(smraw) + 1023u) & ~1023u;
    const uint32_t sA = sb + SMEM_A;
    float2* red = (float2*)(smraw + ((sb - smem_u32(smraw)) + SMEM_RED));

    const int tid = threadIdx.x, lid = tid & 31, wid = tid >> 5;
    const int mwarp = wid >> 1, nwarp = wid & 1;
    const int k = blockIdx.x;
    const int s = cta_start(k);
    const int n = (k < 200 ? 28 : 27);

    int rt = s >> 7;
    int r0 = rt << 7;
    int slot = k - cta_of_tile(rt << 7);

    // prologue: G0 = {A, B_0}, G1 = {B_1}
    pf_a(sA, g_tsb + (size_t)r0 * DDIM, tid);
    pf_b(sb + SMEM_B, g_ntb + (size_t)(s & 127) * 64 * DDIM, tid);
    asm volatile("cp.async.commit_group;" ::: "memory");
    if (n > 1) {
        pf_b(sb + SMEM_B + 16384, g_ntb + (size_t)((s + 1) & 127) * 64 * DDIM, tid);
        asm volatile("cp.async.commit_group;" ::: "memory");
    }

    const uint32_t X = (uint32_t)(lid & 7) << 4;
    const uint32_t cA = ((lid >> 4) & 1) * 16u;
    const uint32_t cB = ((lid >> 3) & 1) * 16u;
    uint32_t rowA[2], rowB[2];
    #pragma unroll
    for (int mt = 0; mt < 2; mt++)
        rowA[mt] = (uint32_t)(mwarp * 32 + mt * 16 + (lid & 15)) * 256u;
    #pragma unroll
    for (int np = 0; np < 2; np++)
        rowB[np] = (uint32_t)(nwarp * 32 + np * 16 + (lid & 7) + ((lid >> 4) & 1) * 8) * 256u;

    float m4[4], s4[4];
    #pragma unroll
    for (int i = 0; i < 4; i++) { m4[i] = -INFINITY; s4[i] = 0.0f; }

    uint32_t areg[2][4][4];   // resident A fragments, k in [0,64)
    int bufsel = 0;
    int prt = 0, pcb = 0;     // prev tile rt / col base (for deferred merge)

    for (int i = 0; i < n; i++) {
        const int t = s + i;
        const int ct = t & 127;
        const bool crossing = (i > 0) && (ct == 0);
        const uint32_t sBuf = sb + SMEM_B + 16384u * (uint32_t)bufsel;

        if (i + 1 < n) asm volatile("cp.async.wait_group 1;" ::: "memory");
        else           asm volatile("cp.async.wait_group 0;" ::: "memory");
        __syncthreads();   // B[i] visible; red[i-1] complete; buf (i-1)%3 free

        if (crossing) {
            // flush row-LSE state for the old rt (old slot), reset
            #pragma unroll
            for (int mt = 0; mt < 2; mt++)
            #pragma unroll
            for (int h = 0; h < 2; h++) {
                const int rs = mt * 2 + h;
                float m = m4[rs], ss = s4[rs];
                #pragma unroll
                for (int d = 1; d <= 2; d <<= 1) {
                    float om = __shfl_xor_sync(0xFFFFFFFFu, m, d);
                    float os = __shfl_xor_sync(0xFFFFFFFFu, ss, d);
                    lse_merge(m, ss, om, os);
                }
                if ((lid & 3) == 0) {
                    const int row = r0 + mwarp * 32 + mt * 16 + (lid >> 2) + h * 8;
                    g_rowp[row][slot * 2 + nwarp] = make_float2(m, ss);
                }
                m4[rs] = -INFINITY; s4[rs] = 0.0f;
            }
            // advance to new rt, reload A (own async group)
            rt = t >> 7;
            r0 = rt << 7;
            slot = k - cta_of_tile(rt << 7);
            pf_a(sA, g_tsb + (size_t)r0 * DDIM, tid);
            asm volatile("cp.async.commit_group;" ::: "memory");
        }

        // deferred column merge of tile i-1 (prev rt/cb)
        if (i > 0 && tid < 64) {
            const float2* rd = red + ((i - 1) & 1) * 512;
            float2 p0 = rd[tid * 4 + 0], p1 = rd[tid * 4 + 1];
            float2 p2 = rd[tid * 4 + 2], p3 = rd[tid * 4 + 3];
            float M = p0.x, S = p0.y;
            lse_merge(M, S, p1.x, p1.y);
            lse_merge(M, S, p2.x, p2.y);
            lse_merge(M, S, p3.x, p3.y);
            g_colp[prt][pcb + tid] = make_float2(M, S);
        }

        // prefetch B for tile i+2 into buf (i+2)%3 == (i-1)%3 (free since barrier)
        if (i + 2 < n) {
            int nb = bufsel + 2; if (nb >= 3) nb -= 3;
            pf_b(sb + SMEM_B + 16384u * (uint32_t)nb,
                 g_ntb + (size_t)((t + 2) & 127) * 64 * DDIM, tid);
            asm volatile("cp.async.commit_group;" ::: "memory");
        }

        if (crossing) {
            // ensure the A reload has landed (leaves at most B[i+2] outstanding)
            if (i + 2 < n) asm volatile("cp.async.wait_group 1;" ::: "memory");
            else           asm volatile("cp.async.wait_group 0;" ::: "memory");
            __syncthreads();   // all threads' A copies visible
        }

        if (i == 0 || crossing) {
            // preload the low-K A fragments into registers
            #pragma unroll
            for (int mt = 0; mt < 2; mt++)
                #pragma unroll
                for (int kt = 0; kt < 4; kt++)
                    ldsm_x4(areg[mt][kt], sA + rowA[mt] + (((uint32_t)kt * 32u + cA) ^ X));
        }

        float acc[2][4][4];
        #pragma unroll
        for (int mt = 0; mt < 2; mt++)
            #pragma unroll
            for (int nt = 0; nt < 4; nt++)
                #pragma unroll
                for (int q = 0; q < 4; q++) acc[mt][nt][q] = 0.0f;

        // k in [0,64): A from registers
        #pragma unroll
        for (int kt = 0; kt < 4; kt++) {
            const uint32_t kb = (uint32_t)kt * 32u;
            uint32_t bfr[4][2];
            #pragma unroll
            for (int np = 0; np < 2; np++) {
                uint32_t tt[4];
                ldsm_x4(tt, sBuf + rowB[np] + ((kb + cB) ^ X));
                bfr[np * 2][0] = tt[0]; bfr[np * 2][1] = tt[1];
                bfr[np * 2 + 1][0] = tt[2]; bfr[np * 2 + 1][1] = tt[3];
            }
            #pragma unroll
            for (int mt = 0; mt < 2; mt++)
                #pragma unroll
                for (int nt = 0; nt < 4; nt++)
                    mma_bf16(acc[mt][nt], areg[mt][kt], bfr[nt]);
        }
        // k in [64,128): A from smem
        #pragma unroll
        for (int kt = 4; kt < 8; kt++) {
            const uint32_t kb = (uint32_t)kt * 32u;
            uint32_t bfr[4][2];
            #pragma unroll
            for (int np = 0; np < 2; np++) {
                uint32_t tt[4];
                ldsm_x4(tt, sBuf + rowB[np] + ((kb + cB) ^ X));
                bfr[np * 2][0] = tt[0]; bfr[np * 2][1] = tt[1];
                bfr[np * 2 + 1][0] = tt[2]; bfr[np * 2 + 1][1] = tt[3];
            }
            #pragma unroll
            for (int mt = 0; mt < 2; mt++) {
                uint32_t afr[4];
                ldsm_x4(afr, sA + rowA[mt] + ((kb + cA) ^ X));
                #pragma unroll
                for (int nt = 0; nt < 4; nt++)
                    mma_bf16(acc[mt][nt], afr, bfr[nt]);
            }
        }

        const int cb = ct * 64;
        const bool masked = ((unsigned)(cb - r0) < 128u);
        float cmx[8], csum[8];

        if (!masked) {
            // ---- row online LSE ----
            #pragma unroll
            for (int mt = 0; mt < 2; mt++)
            #pragma unroll
            for (int h = 0; h < 2; h++) {
                const int rs = mt * 2 + h;
                float amax = acc[mt][0][h * 2];
                #pragma unroll
                for (int nt = 0; nt < 4; nt++)
                    #pragma unroll
                    for (int c = 0; c < 2; c++)
                        amax = fmaxf(amax, acc[mt][nt][h * 2 + c]);
                const float vm = amax * INVT;
                if (vm > m4[rs]) { s4[rs] *= __expf(m4[rs] - vm); m4[rs] = vm; }
                const float thr = (m4[rs] - 25.0f) * (1.0f / INVT);
                #pragma unroll
                for (int nt = 0; nt < 4; nt++)
                    #pragma unroll
                    for (int c = 0; c < 2; c++) {
                        const float a = acc[mt][nt][h * 2 + c];
                        if (a > thr) s4[rs] += __expf(fmaf(a, INVT, -m4[rs]));
                    }
            }
            // ---- col tile max pass ----
            #pragma unroll
            for (int nt = 0; nt < 4; nt++)
            #pragma unroll
            for (int c = 0; c < 2; c++) {
                const int ix = nt * 2 + c;
                float v = acc[0][nt][c];
                v = fmaxf(v, acc[0][nt][2 + c]);
                v = fmaxf(v, acc[1][nt][c]);
                v = fmaxf(v, acc[1][nt][2 + c]);
                cmx[ix] = v;
            }
        } else {
            // ---- masked tile (rare): block-diag mask + diag capture ----
            #pragma unroll
            for (int mt = 0; mt < 2; mt++)
            #pragma unroll
            for (int h = 0; h < 2; h++) {
                const int rs = mt * 2 + h;
                const int gi = r0 + mwarp * 32 + mt * 16 + (lid >> 2) + h * 8;
                #pragma unroll
                for (int nt = 0; nt < 4; nt++)
                    #pragma unroll
                    for (int c = 0; c < 2; c++) {
                        const int gj = cb + nwarp * 32 + nt * 8 + (lid & 3) * 2 + c;
                        const float v = acc[mt][nt][h * 2 + c] * INVT;
                        const bool sameblk = (((gi ^ gj) >> 4) == 0);
                        const bool isdiag = (gi == gj);
                        if (isdiag) g_diag[gi] = v;
                        if (!sameblk || isdiag) {
                            if (v > m4[rs]) { s4[rs] = s4[rs] * __expf(m4[rs] - v) + 1.0f; m4[rs] = v; }
                            else if (v > m4[rs] - 25.0f) s4[rs] += __expf(v - m4[rs]);
                        }
                    }
            }
            #pragma unroll
            for (int nt = 0; nt < 4; nt++)
            #pragma unroll
            for (int c = 0; c < 2; c++) {
                const int ix = nt * 2 + c;
                const int gj = cb + nwarp * 32 + nt * 8 + (lid & 3) * 2 + c;
                float v = -INFINITY;
                #pragma unroll
                for (int mt = 0; mt < 2; mt++)
                    #pragma unroll
                    for (int h = 0; h < 2; h++) {
                        const int gi = r0 + mwarp * 32 + mt * 16 + (lid >> 2) + h * 8;
                        const bool keep = (((gi ^ gj) >> 4) != 0) || (gi == gj);
                        if (keep) v = fmaxf(v, acc[mt][nt][h * 2 + c]);
                    }
                cmx[ix] = v;
            }
        }

        // merge col max across the 8 lanes holding this column (lid>>2 varies)
        #pragma unroll
        for (int ix = 0; ix < 8; ix++) {
            #pragma unroll
            for (int d = 4; d <= 16; d <<= 1)
                cmx[ix] = fmaxf(cmx[ix], __shfl_xor_sync(0xFFFFFFFFu, cmx[ix], d));
        }
        // col sum pass (guarded exp)
        if (!masked) {
            #pragma unroll
            for (int nt = 0; nt < 4; nt++)
            #pragma unroll
            for (int c = 0; c < 2; c++) {
                const int ix = nt * 2 + c;
                const float ML = cmx[ix] * INVT;
                const float thr = cmx[ix] - 0.25f;
                float ss = 0.0f;
                #pragma unroll
                for (int mt = 0; mt < 2; mt++)
                    #pragma unroll
                    for (int h = 0; h < 2; h++) {
                        const float a = acc[mt][nt][h * 2 + c];
                        if (a > thr) ss += __expf(fmaf(a, INVT, -ML));
                    }
                csum[ix] = ss;
            }
        } else {
            #pragma unroll
            for (int nt = 0; nt < 4; nt++)
            #pragma unroll
            for (int c = 0; c < 2; c++) {
                const int ix = nt * 2 + c;
                const int gj = cb + nwarp * 32 + nt * 8 + (lid & 3) * 2 + c;
                const float ML = cmx[ix] * INVT;
                const float thr = cmx[ix] - 0.25f;
                float ss = 0.0f;
                #pragma unroll
                for (int mt = 0; mt < 2; mt++)
                    #pragma unroll
                    for (int h = 0; h < 2; h++) {
                        const int gi = r0 + mwarp * 32 + mt * 16 + (lid >> 2) + h * 8;
                        const bool keep = (((gi ^ gj) >> 4) != 0) || (gi == gj);
                        const float a = acc[mt][nt][h * 2 + c];
                        if (keep && a > thr) ss += __expf(fmaf(a, INVT, -ML));
                    }
                csum[ix] = ss;
            }
        }
        #pragma unroll
        for (int ix = 0; ix < 8; ix++) {
            #pragma unroll
            for (int d = 4; d <= 16; d <<= 1)
                csum[ix] += __shfl_xor_sync(0xFFFFFFFFu, csum[ix], d);
        }
        // write this tile's partials into red[i&1] (read next iteration)
        if (lid < 4) {
            float2* wr = red + (i & 1) * 512;
            #pragma unroll
            for (int nt = 0; nt < 4; nt++)
                #pragma unroll
                for (int c = 0; c < 2; c++)
                    wr[(nwarp * 32 + nt * 8 + lid * 2 + c) * 4 + mwarp] =
                        make_float2(cmx[nt * 2 + c] * INVT, csum[nt * 2 + c]);
        }

        prt = rt; pcb = cb;
        if (++bufsel == 3) bufsel = 0;
    }

    // final tile's deferred merge
    __syncthreads();
    if (tid < 64) {
        const float2* rd = red + ((n - 1) & 1) * 512;
        float2 p0 = rd[tid * 4 + 0], p1 = rd[tid * 4 + 1];
        float2 p2 = rd[tid * 4 + 2], p3 = rd[tid * 4 + 3];
        float M = p0.x, S = p0.y;
        lse_merge(M, S, p1.x, p1.y);
        lse_merge(M, S, p2.x, p2.y);
        lse_merge(M, S, p3.x, p3.y);
        g_colp[prt][pcb + tid] = make_float2(M, S);
    }

    // final row flush (current rt / slot)
    #pragma unroll
    for (int mt = 0; mt < 2; mt++)
    #pragma unroll
    for (int h = 0; h < 2; h++) {
        const int rs = mt * 2 + h;
        float m = m4[rs], ss = s4[rs];
        #pragma unroll
        for (int d = 1; d <= 2; d <<= 1) {
            float om = __shfl_xor_sync(0xFFFFFFFFu, m, d);
            float os = __shfl_xor_sync(0xFFFFFFFFu, ss, d);
            lse_merge(m, ss, om, os);
        }
        if ((lid & 3) == 0) {
            const int row = r0 + mwarp * 32 + mt * 16 + (lid >> 2) + h * 8;
            g_rowp[row][slot * 2 + nwarp] = make_float2(m, ss);
        }
    }
}

// ============ kernel 3: per-index terms + full reduction (last-block) ============
__global__ void cont_fin(float* out) {
    __shared__ float rs[256];
    __shared__ bool last;
    const int tid = threadIdx.x;
    const int i = blockIdx.x * 256 + tid;

    // row LSE: 12 slots, two-pass (max then guarded sum; empty slots are -inf)
    float2 rp[12];
    float M = -INFINITY;
    #pragma unroll
    for (int kk = 0; kk < 12; kk++) { rp[kk] = g_rowp[i][kk]; M = fmaxf(M, rp[kk].x); }
    float S = 0.0f;
    #pragma unroll
    for (int kk = 0; kk < 12; kk++)
        if (rp[kk].x > M - 25.0f) S += rp[kk].y * __expf(rp[kk].x - M);
    const float lser = M + __logf(S);

    // col LSE: 64 partials, two-pass over L2-hot gmem
    float Mc = -INFINITY;
    #pragma unroll 8
    for (int p = 0; p < 64; p++) Mc = fmaxf(Mc, g_colp[p][i].x);
    float Sc = 0.0f;
    #pragma unroll 8
    for (int p = 0; p < 64; p++) {
        float2 q = g_colp[p][i];
        if (q.x > Mc - 25.0f) Sc += q.y * __expf(q.x - Mc);
    }
    const float lsec = Mc + __logf(Sc);

    rs[tid] = 0.5f * (lser + lsec) - g_diag[i];
    __syncthreads();
    for (int o = 128; o > 0; o >>= 1) {
        if (tid < o) rs[tid] += rs[tid + o];
        __syncthreads();
    }
    if (tid == 0) {
        g_bsum[blockIdx.x] = rs[0];
        __threadfence();
        last = (atomicAdd(&g_cnt, 1u) == gridDim.x - 1);
    }
    __syncthreads();
    if (last && tid < 32) {
        __threadfence();
        float v = g_bsum[tid];
        #pragma unroll
        for (int d = 16; d > 0; d >>= 1) v += __shfl_xor_sync(0xFFFFFFFFu, v, d);
        if (tid == 0) {
            float loss = v / (float)NTOT;
            if (isnan(loss) || isinf(loss)) loss = 0.0f;
            out[0] = loss;
            g_cnt = 0;   // reset for next (graph-replayed) launch
        }
    }
}

extern "C" void kernel_launch(void* const* d_in, const int* in_sizes, int n_in,
                              void* d_out, int out_size) {
    const float* ts = (const float*)d_in[0];
    const float* nt = (const float*)d_in[1];
    (void)in_sizes; (void)n_in; (void)out_size;

    conv_kernel<<<1024, 256>>>(ts, nt);
    cudaFuncSetAttribute(cont_mma, cudaFuncAttributeMaxDynamicSharedMemorySize, DYN_SMEM);
    cont_mma<<<NCTA, 256, DYN_SMEM>>>();
    cont_fin<<<32, 256>>>((float*)d_out);
}